// round 1
// baseline (speedup 1.0000x reference)
#include <cuda_runtime.h>
#include <cuda_bf16.h>

// ---------------------------------------------------------------------------
// clDice loss: sigmoid -> 5x soft-skeleton iterations (fused 3x3 erode+open)
// on pred(16 imgs) + gt(16 imgs), then per-image tp/ts reductions + scalar.
//
// Design: warp-strip stencil. Each warp covers 32 columns (28 valid outputs),
// marches down a 128-row segment. Vertical 3-windows in registers, horizontal
// 3-neighborhoods via warp shuffles. No shared memory, no barriers in the hot
// loop -> DRAM-bound.
// ---------------------------------------------------------------------------

#define HH 1024
#define WW 1024
#define NIMG_TOTAL 32            // 16 pred + 16 gt, processed together
#define IMG_ELEMS (HH * WW)

constexpr int STRIP_OUT = 28;                       // valid outputs per warp strip
constexpr int NSTRIPS  = (WW + STRIP_OUT - 1) / STRIP_OUT;  // 37
constexpr int SEG_ROWS = 128;
constexpr int NSEGS    = HH / SEG_ROWS;             // 8
constexpr int WARPS_PER_BLOCK = 8;
constexpr int WARPS_TOTAL = NIMG_TOTAL * NSTRIPS * NSEGS;   // 9472
constexpr int ITER_BLOCKS = WARPS_TOTAL / WARPS_PER_BLOCK;  // 1184

constexpr int RED_BLOCKS_PER_IMG = 64;

// Scratch (device globals: allocation-free per harness rules)
__device__ float g_bufA[(size_t)NIMG_TOTAL * IMG_ELEMS];   // 128 MB
__device__ float g_bufB[(size_t)NIMG_TOTAL * IMG_ELEMS];   // 128 MB
__device__ float2 g_part[16 * RED_BLOCKS_PER_IMG];

__device__ __forceinline__ float f_inf()  { return __int_as_float(0x7f800000); }
__device__ __forceinline__ float f_ninf() { return __int_as_float(0xff800000); }

__device__ __forceinline__ float hmin3(float v) {
    float l = __shfl_up_sync(0xffffffffu, v, 1);
    float r = __shfl_down_sync(0xffffffffu, v, 1);
    return fminf(fminf(l, r), v);
}
__device__ __forceinline__ float hmax3(float v) {
    float l = __shfl_up_sync(0xffffffffu, v, 1);
    float r = __shfl_down_sync(0xffffffffu, v, 1);
    return fmaxf(fmaxf(l, r), v);
}

// ---------------------------------------------------------------------------
// Init: bufA[0:16M)   = sigmoid(logits)   (pred field)
//       bufA[16M:32M) = float(target)     (gt field)
// ---------------------------------------------------------------------------
__global__ __launch_bounds__(256) void init_kernel(
    const float4* __restrict__ logits, const int4* __restrict__ target)
{
    const int n4 = (16 * IMG_ELEMS) / 4;   // 4M float4 per field
    int i = blockIdx.x * blockDim.x + threadIdx.x;
    if (i >= n4) return;

    float4 lg = logits[i];
    float4 p;
    p.x = 1.0f / (1.0f + __expf(-lg.x));
    p.y = 1.0f / (1.0f + __expf(-lg.y));
    p.z = 1.0f / (1.0f + __expf(-lg.z));
    p.w = 1.0f / (1.0f + __expf(-lg.w));
    reinterpret_cast<float4*>(g_bufA)[i] = p;

    int4 tg = target[i];
    float4 tf;
    tf.x = (float)tg.x; tf.y = (float)tg.y; tf.z = (float)tg.z; tf.w = (float)tg.w;
    reinterpret_cast<float4*>(g_bufA)[n4 + i] = tf;
}

// ---------------------------------------------------------------------------
// One soft-skeleton iteration (both fields):
//   eroded = minpool3(x) (pad +inf), opened = maxpool3(eroded) (pad -inf)
//   x' = clip(x - (opened - eroded), 0, 1)
// srcIsA selects ping-pong direction.
// ---------------------------------------------------------------------------
__global__ __launch_bounds__(WARPS_PER_BLOCK * 32) void skel_iter_kernel(int srcIsA)
{
    const float* __restrict__ src = srcIsA ? g_bufA : g_bufB;
    float*       __restrict__ dst = srcIsA ? g_bufB : g_bufA;

    int wid  = blockIdx.x * WARPS_PER_BLOCK + (threadIdx.x >> 5);
    int lane = threadIdx.x & 31;
    if (wid >= WARPS_TOTAL) return;

    int seg   = wid & (NSEGS - 1);
    int t     = wid >> 3;              // NSEGS == 8
    int strip = t % NSTRIPS;
    int img   = t / NSTRIPS;

    int col = strip * STRIP_OUT - 2 + lane;          // global column for this lane
    bool colIn = ((unsigned)col < (unsigned)WW);

    const float* __restrict__ s = src + (size_t)img * IMG_ELEMS + col;
    float*       __restrict__ d = dst + (size_t)img * IMG_ELEMS + col;

    const int r0 = seg * SEG_ROWS;
    const float PINF = f_inf();
    const float NINF = f_ninf();

    auto ld = [&](int r) -> float {
        float v = PINF;
        if (colIn && r >= 0 && r < HH) v = __ldg(s + r * WW);
        return v;
    };

    // x window (rows r-1, r, r+1 relative to produced eroded row), prefetch cn.
    float a = ld(r0 - 2);
    float b = ld(r0 - 1);
    float c = ld(r0);
    float cn = ld(r0 + 1);

    // e0 = eroded(r0-1)
    float vm = fminf(fminf(a, b), c);
    float e0 = hmin3(vm);
    e0 = (colIn && (r0 - 1) >= 0) ? e0 : NINF;

    // e1 = eroded(r0)
    a = b; b = c; c = cn; cn = ld(r0 + 2);
    vm = fminf(fminf(a, b), c);
    float e1 = hmin3(vm);
    e1 = colIn ? e1 : NINF;

    const bool doStore = (lane >= 2) && (lane <= 29) && colIn;

#pragma unroll 4
    for (int oy = r0; oy < r0 + SEG_ROWS; ++oy) {
        // advance window: a = x[oy], b = x[oy+1], c = x[oy+2]
        a = b; b = c; c = cn;
        cn = ld(oy + 3);

        // e2 = eroded(oy+1)
        vm = fminf(fminf(a, b), c);
        float e2 = hmin3(vm);
        e2 = (colIn && (oy + 1) < HH) ? e2 : NINF;

        // opened(oy) = maxpool3 of eroded rows oy-1..oy+1
        float om = fmaxf(fmaxf(e0, e1), e2);
        float op = hmax3(om);

        // x' = clip(x - (opened - eroded), 0, 1); a == x[oy], e1 == eroded(oy)
        float out = __saturatef(a - (op - e1));
        if (doStore) d[oy * WW] = out;

        e0 = e1; e1 = e2;
    }
}

// ---------------------------------------------------------------------------
// Reduction: per image b (0..15):
//   tp[b] = sum(skel_pred * target),  ts[b] = sum(skel_gt * sigmoid(logits))
// skeletons live in g_bufB after 5 iterations.
// ---------------------------------------------------------------------------
__global__ __launch_bounds__(256) void reduce_kernel(
    const float* __restrict__ logits, const int* __restrict__ target)
{
    const int img = blockIdx.y;          // 0..15
    const int blk = blockIdx.x;          // 0..63
    const int CHUNK4 = IMG_ELEMS / (RED_BLOCKS_PER_IMG * 4);   // 4096

    size_t base4 = ((size_t)img * IMG_ELEMS) / 4 + (size_t)blk * CHUNK4;

    const float4* __restrict__ sp = reinterpret_cast<const float4*>(g_bufB) + base4;
    const float4* __restrict__ sg = reinterpret_cast<const float4*>(g_bufB)
                                    + (size_t)(16 * IMG_ELEMS) / 4 + base4;
    const float4* __restrict__ lg = reinterpret_cast<const float4*>(logits) + base4;
    const int4*   __restrict__ tg = reinterpret_cast<const int4*>(target) + base4;

    float tp = 0.0f, ts = 0.0f;
    for (int k = threadIdx.x; k < CHUNK4; k += blockDim.x) {
        float4 p = sp[k];
        int4   t = tg[k];
        tp += p.x * (float)t.x + p.y * (float)t.y + p.z * (float)t.z + p.w * (float)t.w;

        float4 g = sg[k];
        float4 l = lg[k];
        ts += g.x * (1.0f / (1.0f + __expf(-l.x)))
            + g.y * (1.0f / (1.0f + __expf(-l.y)))
            + g.z * (1.0f / (1.0f + __expf(-l.z)))
            + g.w * (1.0f / (1.0f + __expf(-l.w)));
    }

    // block reduction (deterministic: no atomics)
    for (int o = 16; o > 0; o >>= 1) {
        tp += __shfl_down_sync(0xffffffffu, tp, o);
        ts += __shfl_down_sync(0xffffffffu, ts, o);
    }
    __shared__ float s_tp[8], s_ts[8];
    int wid = threadIdx.x >> 5, lane = threadIdx.x & 31;
    if (lane == 0) { s_tp[wid] = tp; s_ts[wid] = ts; }
    __syncthreads();
    if (threadIdx.x == 0) {
        float atp = 0.0f, ats = 0.0f;
#pragma unroll
        for (int i = 0; i < 8; ++i) { atp += s_tp[i]; ats += s_ts[i]; }
        g_part[img * RED_BLOCKS_PER_IMG + blk] = make_float2(atp, ats);
    }
}

// ---------------------------------------------------------------------------
// Final: combine partials, clDice per image, mean(1 - cldice) -> d_out[0]
// ---------------------------------------------------------------------------
__global__ void final_kernel(float* __restrict__ out)
{
    int t = threadIdx.x;   // 32 threads
    float contrib = 0.0f;
    if (t < 16) {
        double tp = 0.0, ts = 0.0;
        for (int b = 0; b < RED_BLOCKS_PER_IMG; ++b) {
            float2 v = g_part[t * RED_BLOCKS_PER_IMG + b];
            tp += (double)v.x;
            ts += (double)v.y;
        }
        const double eps = 1e-6;
        double den = tp + ts;
        double cl = (den > 0.0) ? (2.0 * tp * ts + eps) / (den + eps) : 1.0;
        cl = fmin(fmax(cl, 0.0), 1.0);
        contrib = (float)(1.0 - cl);
    }
    for (int o = 16; o > 0; o >>= 1)
        contrib += __shfl_down_sync(0xffffffffu, contrib, o);
    if (t == 0) out[0] = contrib * (1.0f / 16.0f);
}

// ---------------------------------------------------------------------------
extern "C" void kernel_launch(void* const* d_in, const int* in_sizes, int n_in,
                              void* d_out, int out_size)
{
    (void)in_sizes; (void)n_in; (void)out_size;
    const float* logits = (const float*)d_in[0];
    const int*   target = (const int*)d_in[1];
    float*       out    = (float*)d_out;

    // init: sigmoid(logits) and float(target) into bufA
    {
        int n4 = (16 * IMG_ELEMS) / 4;
        init_kernel<<<(n4 + 255) / 256, 256>>>(
            (const float4*)logits, (const int4*)target);
    }

    // 5 soft-skeleton iterations, ping-pong A->B->A->B->A->B (final in B)
    skel_iter_kernel<<<ITER_BLOCKS, WARPS_PER_BLOCK * 32>>>(1);
    skel_iter_kernel<<<ITER_BLOCKS, WARPS_PER_BLOCK * 32>>>(0);
    skel_iter_kernel<<<ITER_BLOCKS, WARPS_PER_BLOCK * 32>>>(1);
    skel_iter_kernel<<<ITER_BLOCKS, WARPS_PER_BLOCK * 32>>>(0);
    skel_iter_kernel<<<ITER_BLOCKS, WARPS_PER_BLOCK * 32>>>(1);

    // per-image tp/ts partials
    {
        dim3 grid(RED_BLOCKS_PER_IMG, 16);
        reduce_kernel<<<grid, 256>>>(logits, target);
    }

    // scalar epilogue
    final_kernel<<<1, 32>>>(out);
}

// round 2
// speedup vs baseline: 1.0713x; 1.0713x over previous
#include <cuda_runtime.h>
#include <cuda_bf16.h>

// ---------------------------------------------------------------------------
// clDice loss, fully fused:
//   iter1: sigmoid(logits)/float(target) -> soft-skel step -> bufB
//   iter2..4: ping-pong bufB/bufA
//   iter5: skel step + tp/ts dot-product accumulation (no store)
//   final: combine partials, clDice, mean.
//
// Stencil design: warp-strip, each lane owns 4 aligned columns (float4),
// warp covers 128 aligned columns. Vertical windows in registers, horizontal
// windows via 2 warp shuffles per stage. Cross-strip halo (2 columns each
// side) via one predicated LDG.128 on lanes 0/31. No smem in the hot loop.
// ---------------------------------------------------------------------------

#define HH 1024
#define WW 1024
#define IMG (HH * WW)

constexpr int SEG    = 32;            // rows per warp segment
constexpr int NSEG   = HH / SEG;      // 32
constexpr int STRIPS = 8;             // 128 cols per warp
constexpr int WPB    = 8;             // warps per block
constexpr int BLOCKS_PER_IMG = STRIPS * NSEG / WPB;   // 32
constexpr int NBLOCKS = 32 * BLOCKS_PER_IMG;          // 1024

__device__ float g_bufA[(size_t)32 * IMG];   // 128 MB
__device__ float g_bufB[(size_t)32 * IMG];   // 128 MB
__device__ float g_part[NBLOCKS];

__device__ __forceinline__ float f_inf()  { return __int_as_float(0x7f800000); }
__device__ __forceinline__ float f_ninf() { return __int_as_float(0xff800000); }
__device__ __forceinline__ float sig1(float x) { return 1.0f / (1.0f + __expf(-x)); }
__device__ __forceinline__ float min3f(float a, float b, float c) { return fminf(fminf(a, b), c); }
__device__ __forceinline__ float max3f(float a, float b, float c) { return fmaxf(fmaxf(a, b), c); }

// MODE: 0 = read logits/target (fused init), write dst
//       1 = read src, write dst
//       2 = read src, accumulate tp/ts partials (no dst write)
template<int MODE>
__global__ __launch_bounds__(WPB * 32)
void skel_kernel(int srcIsA,
                 const float* __restrict__ logits,
                 const int* __restrict__ target)
{
    const int lane  = threadIdx.x & 31;
    const int w     = threadIdx.x >> 5;
    const int img   = blockIdx.x / BLOCKS_PER_IMG;
    const int u     = (blockIdx.x % BLOCKS_PER_IMG) * WPB + w;
    const int strip = u & (STRIPS - 1);
    const int seg   = u / STRIPS;
    const int colBase = strip * 128;
    const int col     = colBase + lane * 4;
    const bool isPred = (img < 16);
    const int  imgF   = isPred ? img : img - 16;

    const float PINF = f_inf();
    const float NINF = f_ninf();

    const bool hl = (lane == 0);
    const bool hr = (lane == 31);
    const bool hv = (hl && strip > 0) || (hr && strip < STRIPS - 1);
    const bool hedge = (hl && strip == 0) || (hr && strip == STRIPS - 1);
    const int  hcol  = hl ? (colBase - 4) : (colBase + 128);

    const float* src = srcIsA ? g_bufA : g_bufB;
    float*       dst = srcIsA ? g_bufB : g_bufA;

    const float* __restrict__ srcI = src + (size_t)img * IMG;
    float*       __restrict__ dstI = dst + (size_t)img * IMG + col;
    const float* __restrict__ lgI  = logits + (size_t)imgF * IMG;
    const int*   __restrict__ tgI  = target + (size_t)imgF * IMG;

    // main-row load (4 aligned columns), +inf outside image rows
    auto ldm = [&](int r) -> float4 {
        float4 v = make_float4(PINF, PINF, PINF, PINF);
        if ((unsigned)r < (unsigned)HH) {
            if (MODE == 0) {
                if (isPred) {
                    float4 t = __ldg((const float4*)(lgI + r * WW + col));
                    v = make_float4(sig1(t.x), sig1(t.y), sig1(t.z), sig1(t.w));
                } else {
                    int4 t = __ldg((const int4*)(tgI + r * WW + col));
                    v = make_float4((float)t.x, (float)t.y, (float)t.z, (float)t.w);
                }
            } else {
                v = __ldg((const float4*)(srcI + r * WW + col));
            }
        }
        return v;
    };
    // halo load: lane0 -> cols (base-2,base-1) via .zw ; lane31 -> (base+128,+129) via .xy
    auto ldh = [&](int r) -> float2 {
        float2 v = make_float2(PINF, PINF);
        if (hv && (unsigned)r < (unsigned)HH) {
            if (MODE == 0) {
                if (isPred) {
                    float4 t = __ldg((const float4*)(lgI + r * WW + hcol));
                    float2 raw = hl ? make_float2(t.z, t.w) : make_float2(t.x, t.y);
                    v = make_float2(sig1(raw.x), sig1(raw.y));
                } else {
                    int4 t = __ldg((const int4*)(tgI + r * WW + hcol));
                    v = hl ? make_float2((float)t.z, (float)t.w)
                           : make_float2((float)t.x, (float)t.y);
                }
            } else {
                float4 t = __ldg((const float4*)(srcI + r * WW + hcol));
                v = hl ? make_float2(t.z, t.w) : make_float2(t.x, t.y);
            }
        }
        return v;
    };

    // erode one row: vertical min of (A,B,C) then horizontal min3.
    // E = eroded for own 4 cols; EH = eroded halo col (-1 on lane0, 128 on lane31)
    auto erode = [&](const float4& A, const float4& B, const float4& C,
                     const float2& HA, const float2& HB, const float2& HC,
                     float4& E, float& EH) {
        float4 vm;
        vm.x = min3f(A.x, B.x, C.x); vm.y = min3f(A.y, B.y, C.y);
        vm.z = min3f(A.z, B.z, C.z); vm.w = min3f(A.w, B.w, C.w);
        float2 hvm;
        hvm.x = min3f(HA.x, HB.x, HC.x); hvm.y = min3f(HA.y, HB.y, HC.y);
        float l = __shfl_up_sync(0xffffffffu, vm.w, 1);   if (hl) l = hvm.y;
        float r = __shfl_down_sync(0xffffffffu, vm.x, 1); if (hr) r = hvm.x;
        E.x = min3f(l, vm.x, vm.y);
        E.y = min3f(vm.x, vm.y, vm.z);
        E.z = min3f(vm.y, vm.z, vm.w);
        E.w = min3f(vm.z, vm.w, r);
        EH = fminf(fminf(hvm.x, hvm.y), hl ? vm.x : vm.w);
        if (hedge) EH = NINF;   // eroded outside image = -inf for the opening
    };

    const int r0 = seg * SEG;

    float4 a = ldm(r0 - 2), b = ldm(r0 - 1), c = ldm(r0), cn = ldm(r0 + 1);
    float2 ha = ldh(r0 - 2), hb = ldh(r0 - 1), hc = ldh(r0), hcn = ldh(r0 + 1);

    float4 e0, e1, e2;
    float  eh0, eh1, eh2;

    erode(a, b, c, ha, hb, hc, e0, eh0);           // eroded(r0-1)
    if (r0 - 1 < 0) { e0 = make_float4(NINF, NINF, NINF, NINF); eh0 = NINF; }

    a = b; b = c; c = cn; cn = ldm(r0 + 2);
    ha = hb; hb = hc; hc = hcn; hcn = ldh(r0 + 2);
    erode(a, b, c, ha, hb, hc, e1, eh1);           // eroded(r0)

    float acc = 0.0f;

#pragma unroll 4
    for (int oy = r0; oy < r0 + SEG; ++oy) {
        a = b; b = c; c = cn; cn = ldm(oy + 3);
        ha = hb; hb = hc; hc = hcn; hcn = ldh(oy + 3);

        erode(a, b, c, ha, hb, hc, e2, eh2);       // eroded(oy+1)
        if (oy + 1 >= HH) { e2 = make_float4(NINF, NINF, NINF, NINF); eh2 = NINF; }

        float4 om;
        om.x = max3f(e0.x, e1.x, e2.x); om.y = max3f(e0.y, e1.y, e2.y);
        om.z = max3f(e0.z, e1.z, e2.z); om.w = max3f(e0.w, e1.w, e2.w);
        float omh = max3f(eh0, eh1, eh2);
        float l = __shfl_up_sync(0xffffffffu, om.w, 1);   if (hl) l = omh;
        float r = __shfl_down_sync(0xffffffffu, om.x, 1); if (hr) r = omh;
        float4 op;
        op.x = max3f(l, om.x, om.y);
        op.y = max3f(om.x, om.y, om.z);
        op.z = max3f(om.y, om.z, om.w);
        op.w = max3f(om.z, om.w, r);

        float4 out;   // a == x[oy], e1 == eroded(oy)
        out.x = __saturatef(a.x - (op.x - e1.x));
        out.y = __saturatef(a.y - (op.y - e1.y));
        out.z = __saturatef(a.z - (op.z - e1.z));
        out.w = __saturatef(a.w - (op.w - e1.w));

        if (MODE < 2) {
            *(float4*)(dstI + oy * WW) = out;
        } else {
            if (isPred) {   // tp += skel_pred * target
                int4 t = __ldg((const int4*)(tgI + oy * WW + col));
                acc += out.x * (float)t.x + out.y * (float)t.y
                     + out.z * (float)t.z + out.w * (float)t.w;
            } else {        // ts += skel_gt * sigmoid(logits)
                float4 t = __ldg((const float4*)(lgI + oy * WW + col));
                acc += out.x * sig1(t.x) + out.y * sig1(t.y)
                     + out.z * sig1(t.z) + out.w * sig1(t.w);
            }
        }

        e0 = e1; e1 = e2; eh0 = eh1; eh1 = eh2;
    }

    if (MODE == 2) {
        for (int o = 16; o > 0; o >>= 1)
            acc += __shfl_down_sync(0xffffffffu, acc, o);
        __shared__ float s[WPB];
        if (lane == 0) s[w] = acc;
        __syncthreads();
        if (threadIdx.x == 0) {
            float t = 0.0f;
#pragma unroll
            for (int i = 0; i < WPB; ++i) t += s[i];
            g_part[blockIdx.x] = t;
        }
    }
}

// ---------------------------------------------------------------------------
__global__ void final_kernel(float* __restrict__ out)
{
    int t = threadIdx.x;   // 32 threads
    float contrib = 0.0f;
    if (t < 16) {
        double tp = 0.0, ts = 0.0;
        for (int k = 0; k < BLOCKS_PER_IMG; ++k) {
            tp += (double)g_part[t * BLOCKS_PER_IMG + k];
            ts += (double)g_part[(t + 16) * BLOCKS_PER_IMG + k];
        }
        const double eps = 1e-6;
        double den = tp + ts;
        double cl = (den > 0.0) ? (2.0 * tp * ts + eps) / (den + eps) : 1.0;
        cl = fmin(fmax(cl, 0.0), 1.0);
        contrib = (float)(1.0 - cl);
    }
    for (int o = 16; o > 0; o >>= 1)
        contrib += __shfl_down_sync(0xffffffffu, contrib, o);
    if (t == 0) out[0] = contrib * (1.0f / 16.0f);
}

// ---------------------------------------------------------------------------
extern "C" void kernel_launch(void* const* d_in, const int* in_sizes, int n_in,
                              void* d_out, int out_size)
{
    (void)in_sizes; (void)n_in; (void)out_size;
    const float* lg = (const float*)d_in[0];
    const int*   tg = (const int*)d_in[1];
    float*       out = (float*)d_out;

    // iter1 (fused sigmoid/convert) -> bufB   (srcIsA=1 selects dst=bufB)
    skel_kernel<0><<<NBLOCKS, WPB * 32>>>(1, lg, tg);
    // iter2: B -> A
    skel_kernel<1><<<NBLOCKS, WPB * 32>>>(0, lg, tg);
    // iter3: A -> B
    skel_kernel<1><<<NBLOCKS, WPB * 32>>>(1, lg, tg);
    // iter4: B -> A
    skel_kernel<1><<<NBLOCKS, WPB * 32>>>(0, lg, tg);
    // iter5 (fused reduce): A -> partials
    skel_kernel<2><<<NBLOCKS, WPB * 32>>>(1, lg, tg);

    final_kernel<<<1, 32>>>(out);
}

// round 3
// speedup vs baseline: 1.2745x; 1.1896x over previous
#include <cuda_runtime.h>
#include <cuda_fp16.h>

// ---------------------------------------------------------------------------
// clDice loss, fused, fp16 intermediates (fp32 compute):
//   iter1: sigmoid(logits)/float(target) -> skel step -> bufB (half)
//   iter2..4: ping-pong half buffers
//   iter5: skel step + tp/ts accumulation (no store)
// Warp-strip stencil: lane owns 4 aligned cols, warp = 128 cols.
// ---------------------------------------------------------------------------

#define HH 1024
#define WW 1024
#define IMG (HH * WW)

constexpr int SEG    = 32;            // rows per warp segment
constexpr int NSEG   = HH / SEG;      // 32
constexpr int STRIPS = 8;             // 128 cols per warp
constexpr int WPB    = 8;             // warps per block
constexpr int BLOCKS_PER_IMG = STRIPS * NSEG / WPB;   // 32
constexpr int NBLOCKS_ALL   = 32 * BLOCKS_PER_IMG;    // 1024 (both fields)
constexpr int NBLOCKS_FIELD = 16 * BLOCKS_PER_IMG;    // 512  (one field)

__device__ __half g_bufA[(size_t)32 * IMG];   // 64 MB
__device__ __half g_bufB[(size_t)32 * IMG];   // 64 MB
__device__ float  g_part[NBLOCKS_ALL];

__device__ __forceinline__ float f_inf()  { return __int_as_float(0x7f800000); }
__device__ __forceinline__ float f_ninf() { return __int_as_float(0xff800000); }
__device__ __forceinline__ float sig1(float x) { return 1.0f / (1.0f + __expf(-x)); }
__device__ __forceinline__ float min3f(float a, float b, float c) { return fminf(fminf(a, b), c); }
__device__ __forceinline__ float max3f(float a, float b, float c) { return fmaxf(fmaxf(a, b), c); }

__device__ __forceinline__ float4 h4_to_f4(uint2 u) {
    __half2 lo = *reinterpret_cast<__half2*>(&u.x);
    __half2 hi = *reinterpret_cast<__half2*>(&u.y);
    float2 a = __half22float2(lo);
    float2 b = __half22float2(hi);
    return make_float4(a.x, a.y, b.x, b.y);
}
__device__ __forceinline__ uint2 f4_to_h4(float4 v) {
    __half2 lo = __floats2half2_rn(v.x, v.y);
    __half2 hi = __floats2half2_rn(v.z, v.w);
    uint2 u;
    u.x = *reinterpret_cast<unsigned*>(&lo);
    u.y = *reinterpret_cast<unsigned*>(&hi);
    return u;
}
__device__ __forceinline__ float2 h2_to_f2(unsigned u) {
    __half2 h = *reinterpret_cast<__half2*>(&u);
    return __half22float2(h);
}

// MODE: 0 = read logits/target (fused init), write dst  [FIELD = 0 pred, 1 gt]
//       1 = read src, write dst (field-agnostic; grid covers 32 images)
//       2 = read src, accumulate tp/ts partials          [FIELD = 0 pred, 1 gt]
template<int MODE, int FIELD>
__global__ __launch_bounds__(WPB * 32)
void skel_kernel(int srcIsA,
                 const float* __restrict__ logits,
                 const int* __restrict__ target)
{
    const int lane  = threadIdx.x & 31;
    const int w     = threadIdx.x >> 5;
    const int imgL  = blockIdx.x / BLOCKS_PER_IMG;           // local img index
    const int img   = (MODE == 1) ? imgL : (FIELD * 16 + imgL);
    const int imgF  = (MODE == 1) ? 0 : imgL;                // index into logits/target
    const int u     = (blockIdx.x % BLOCKS_PER_IMG) * WPB + w;
    const int strip = u & (STRIPS - 1);
    const int seg   = u / STRIPS;
    const int colBase = strip * 128;
    const int col     = colBase + lane * 4;

    const float PINF = f_inf();
    const float NINF = f_ninf();

    const bool hl = (lane == 0);
    const bool hr = (lane == 31);
    const bool hv = (hl && strip > 0) || (hr && strip < STRIPS - 1);
    const bool hedge = (hl && strip == 0) || (hr && strip == STRIPS - 1);
    const int  hcol2 = hl ? (colBase - 2) : (colBase + 128);   // 2 halo cols

    const __half* src = srcIsA ? g_bufA : g_bufB;
    __half*       dst = srcIsA ? g_bufB : g_bufA;

    const __half* __restrict__ srcI = src + (size_t)img * IMG;
    __half*       __restrict__ dstI = dst + (size_t)img * IMG + col;
    const float* __restrict__ lgI  = logits + (size_t)imgF * IMG;
    const int*   __restrict__ tgI  = target + (size_t)imgF * IMG;

    // main-row load (4 aligned columns) in fp32, +inf outside image rows
    auto ldm = [&](int r) -> float4 {
        float4 v = make_float4(PINF, PINF, PINF, PINF);
        if ((unsigned)r < (unsigned)HH) {
            if (MODE == 0) {
                if (FIELD == 0) {
                    float4 t = __ldg((const float4*)(lgI + r * WW + col));
                    v = make_float4(sig1(t.x), sig1(t.y), sig1(t.z), sig1(t.w));
                } else {
                    int4 t = __ldg((const int4*)(tgI + r * WW + col));
                    v = make_float4((float)t.x, (float)t.y, (float)t.z, (float)t.w);
                }
            } else {
                uint2 u8 = __ldg((const uint2*)(srcI + r * WW + col));
                v = h4_to_f4(u8);
            }
        }
        return v;
    };
    // halo load: 2 columns (lane0: base-2..base-1, lane31: base+128..base+129)
    auto ldh = [&](int r) -> float2 {
        float2 v = make_float2(PINF, PINF);
        if (hv && (unsigned)r < (unsigned)HH) {
            if (MODE == 0) {
                if (FIELD == 0) {
                    float2 t = __ldg((const float2*)(lgI + r * WW + hcol2));
                    v = make_float2(sig1(t.x), sig1(t.y));
                } else {
                    int2 t = __ldg((const int2*)(tgI + r * WW + hcol2));
                    v = make_float2((float)t.x, (float)t.y);
                }
            } else {
                unsigned t = __ldg((const unsigned*)(srcI + r * WW + hcol2));
                v = h2_to_f2(t);
            }
        }
        return v;
    };

    // erode one row: vertical min of (A,B,C) then horizontal min3.
    auto erode = [&](const float4& A, const float4& B, const float4& C,
                     const float2& HA, const float2& HB, const float2& HC,
                     float4& E, float& EH) {
        float4 vm;
        vm.x = min3f(A.x, B.x, C.x); vm.y = min3f(A.y, B.y, C.y);
        vm.z = min3f(A.z, B.z, C.z); vm.w = min3f(A.w, B.w, C.w);
        float2 hvm;
        hvm.x = min3f(HA.x, HB.x, HC.x); hvm.y = min3f(HA.y, HB.y, HC.y);
        float l = __shfl_up_sync(0xffffffffu, vm.w, 1);   if (hl) l = hvm.y;
        float r = __shfl_down_sync(0xffffffffu, vm.x, 1); if (hr) r = hvm.x;
        E.x = min3f(l, vm.x, vm.y);
        E.y = min3f(vm.x, vm.y, vm.z);
        E.z = min3f(vm.y, vm.z, vm.w);
        E.w = min3f(vm.z, vm.w, r);
        EH = fminf(fminf(hvm.x, hvm.y), hl ? vm.x : vm.w);
        if (hedge) EH = NINF;   // no eroded value outside the image
    };

    const int r0 = seg * SEG;

    float4 a = ldm(r0 - 2), b = ldm(r0 - 1), c = ldm(r0), cn = ldm(r0 + 1);
    float2 ha = ldh(r0 - 2), hb = ldh(r0 - 1), hc = ldh(r0), hcn = ldh(r0 + 1);

    float4 e0, e1, e2;
    float  eh0, eh1, eh2;

    erode(a, b, c, ha, hb, hc, e0, eh0);           // eroded(r0-1)
    if (r0 - 1 < 0) { e0 = make_float4(NINF, NINF, NINF, NINF); eh0 = NINF; }

    a = b; b = c; c = cn; cn = ldm(r0 + 2);
    ha = hb; hb = hc; hc = hcn; hcn = ldh(r0 + 2);
    erode(a, b, c, ha, hb, hc, e1, eh1);           // eroded(r0)

    float acc = 0.0f;

#pragma unroll 4
    for (int oy = r0; oy < r0 + SEG; ++oy) {
        a = b; b = c; c = cn; cn = ldm(oy + 3);
        ha = hb; hb = hc; hc = hcn; hcn = ldh(oy + 3);

        erode(a, b, c, ha, hb, hc, e2, eh2);       // eroded(oy+1)
        if (oy + 1 >= HH) { e2 = make_float4(NINF, NINF, NINF, NINF); eh2 = NINF; }

        float4 om;
        om.x = max3f(e0.x, e1.x, e2.x); om.y = max3f(e0.y, e1.y, e2.y);
        om.z = max3f(e0.z, e1.z, e2.z); om.w = max3f(e0.w, e1.w, e2.w);
        float omh = max3f(eh0, eh1, eh2);
        float l = __shfl_up_sync(0xffffffffu, om.w, 1);   if (hl) l = omh;
        float r = __shfl_down_sync(0xffffffffu, om.x, 1); if (hr) r = omh;
        float4 op;
        op.x = max3f(l, om.x, om.y);
        op.y = max3f(om.x, om.y, om.z);
        op.z = max3f(om.y, om.z, om.w);
        op.w = max3f(om.z, om.w, r);

        float4 out;   // a == x[oy], e1 == eroded(oy)
        out.x = __saturatef(a.x - (op.x - e1.x));
        out.y = __saturatef(a.y - (op.y - e1.y));
        out.z = __saturatef(a.z - (op.z - e1.z));
        out.w = __saturatef(a.w - (op.w - e1.w));

        if (MODE < 2) {
            *(uint2*)(dstI + oy * WW) = f4_to_h4(out);
        } else {
            if (FIELD == 0) {   // tp += skel_pred * target
                int4 t = __ldg((const int4*)(tgI + oy * WW + col));
                acc += out.x * (float)t.x + out.y * (float)t.y
                     + out.z * (float)t.z + out.w * (float)t.w;
            } else {            // ts += skel_gt * sigmoid(logits)
                float4 t = __ldg((const float4*)(lgI + oy * WW + col));
                acc += out.x * sig1(t.x) + out.y * sig1(t.y)
                     + out.z * sig1(t.z) + out.w * sig1(t.w);
            }
        }

        e0 = e1; e1 = e2; eh0 = eh1; eh1 = eh2;
    }

    if (MODE == 2) {
        for (int o = 16; o > 0; o >>= 1)
            acc += __shfl_down_sync(0xffffffffu, acc, o);
        __shared__ float s[WPB];
        if (lane == 0) s[w] = acc;
        __syncthreads();
        if (threadIdx.x == 0) {
            float t = 0.0f;
#pragma unroll
            for (int i = 0; i < WPB; ++i) t += s[i];
            // pred partials in [0,512), gt partials in [512,1024)
            g_part[FIELD * NBLOCKS_FIELD + blockIdx.x] = t;
        }
    }
}

// ---------------------------------------------------------------------------
__global__ void final_kernel(float* __restrict__ out)
{
    int t = threadIdx.x;   // 32 threads
    float contrib = 0.0f;
    if (t < 16) {
        double tp = 0.0, ts = 0.0;
        for (int k = 0; k < BLOCKS_PER_IMG; ++k) {
            tp += (double)g_part[t * BLOCKS_PER_IMG + k];
            ts += (double)g_part[NBLOCKS_FIELD + t * BLOCKS_PER_IMG + k];
        }
        const double eps = 1e-6;
        double den = tp + ts;
        double cl = (den > 0.0) ? (2.0 * tp * ts + eps) / (den + eps) : 1.0;
        cl = fmin(fmax(cl, 0.0), 1.0);
        contrib = (float)(1.0 - cl);
    }
    for (int o = 16; o > 0; o >>= 1)
        contrib += __shfl_down_sync(0xffffffffu, contrib, o);
    if (t == 0) out[0] = contrib * (1.0f / 16.0f);
}

// ---------------------------------------------------------------------------
extern "C" void kernel_launch(void* const* d_in, const int* in_sizes, int n_in,
                              void* d_out, int out_size)
{
    (void)in_sizes; (void)n_in; (void)out_size;
    const float* lg = (const float*)d_in[0];
    const int*   tg = (const int*)d_in[1];
    float*       out = (float*)d_out;

    // iter1 (fused sigmoid/convert) -> bufB   (srcIsA=1 selects dst=bufB)
    skel_kernel<0, 0><<<NBLOCKS_FIELD, WPB * 32>>>(1, lg, tg);   // pred
    skel_kernel<0, 1><<<NBLOCKS_FIELD, WPB * 32>>>(1, lg, tg);   // gt
    // iter2: B -> A
    skel_kernel<1, 0><<<NBLOCKS_ALL, WPB * 32>>>(0, lg, tg);
    // iter3: A -> B
    skel_kernel<1, 0><<<NBLOCKS_ALL, WPB * 32>>>(1, lg, tg);
    // iter4: B -> A
    skel_kernel<1, 0><<<NBLOCKS_ALL, WPB * 32>>>(0, lg, tg);
    // iter5 (fused reduce): A -> partials
    skel_kernel<2, 0><<<NBLOCKS_FIELD, WPB * 32>>>(1, lg, tg);   // pred: tp
    skel_kernel<2, 1><<<NBLOCKS_FIELD, WPB * 32>>>(1, lg, tg);   // gt:   ts

    final_kernel<<<1, 32>>>(out);
}

// round 4
// speedup vs baseline: 1.7372x; 1.3630x over previous
#include <cuda_runtime.h>
#include <cuda_fp16.h>
#include <cstring>

// ---------------------------------------------------------------------------
// clDice loss, fused, fp16 storage AND half2-SIMD stencil compute.
//   iter1 (MODE0): sigmoid(logits)/float(target) -> skel step -> bufB
//   iter2..4 (MODE1): ping-pong half buffers
//   iter5 (MODE2): skel step + tp/ts accumulation (no store)
// Warp-strip: each lane owns 8 aligned columns (4 x half2), warp = 256 cols.
// Horizontal 3-windows built with byte_perm shifts + 2 boundary shuffles.
// ---------------------------------------------------------------------------

#define HH 1024
#define WW 1024
#define IMG (HH * WW)

constexpr int SEG    = 32;                 // rows per warp segment
constexpr int NSEG   = HH / SEG;           // 32
constexpr int STRIPS = 4;                  // 256 cols per warp
constexpr int WPB    = 8;                  // warps per block
constexpr int WARPS_PER_IMG  = STRIPS * NSEG;          // 128
constexpr int BLOCKS_PER_IMG = WARPS_PER_IMG / WPB;    // 16
constexpr int NBLOCKS        = 32 * BLOCKS_PER_IMG;    // 512 (both fields)

__device__ __half g_bufA[(size_t)32 * IMG];   // 64 MB
__device__ __half g_bufB[(size_t)32 * IMG];   // 64 MB
__device__ float  g_part[NBLOCKS];

__device__ __forceinline__ unsigned U(__half2 h) { unsigned u; memcpy(&u, &h, 4); return u; }
__device__ __forceinline__ __half2  H(unsigned u) { __half2 h; memcpy(&h, &u, 4); return h; }
__device__ __forceinline__ __half2  PINF2() { return H(0x7C007C00u); }
__device__ __forceinline__ __half2  NINF2() { return H(0xFC00FC00u); }
__device__ __forceinline__ float    sig1(float x) { return 1.0f / (1.0f + __expf(-x)); }
// {a.high, b.low} -> packed window-shift helper
__device__ __forceinline__ __half2  mid(__half2 a, __half2 b) {
    return H(__byte_perm(U(a), U(b), 0x5432));
}

struct Row { __half2 m[4]; __half2 h; };   // 8 main cols + 2 halo cols

// MODE: 0 = read logits/target (fused init), write dst
//       1 = read src, write dst
//       2 = read src, accumulate tp/ts block partials (no store)
template<int MODE>
__global__ __launch_bounds__(WPB * 32)
void skel_kernel(int srcIsA,
                 const float* __restrict__ logits,
                 const int* __restrict__ target)
{
    const int lane  = threadIdx.x & 31;
    const int w     = threadIdx.x >> 5;
    const int img   = blockIdx.x / BLOCKS_PER_IMG;      // 0..31 (0..15 pred, 16..31 gt)
    const bool isPred = (img < 16);
    const int imgF  = img & 15;
    const int u     = (blockIdx.x % BLOCKS_PER_IMG) * WPB + w;
    const int strip = u & (STRIPS - 1);
    const int seg   = u >> 2;
    const int colBase = strip * 256;
    const int col     = colBase + lane * 8;

    const bool hl = (lane == 0);
    const bool hr = (lane == 31);
    const bool hv = (hl && strip > 0) || (hr && strip < STRIPS - 1);
    const bool hedge = (hl && strip == 0) || (hr && strip == STRIPS - 1);
    const int  hcol  = hl ? (colBase - 2) : (colBase + 256);

    const __half* src = srcIsA ? g_bufA : g_bufB;
    __half*       dst = srcIsA ? g_bufB : g_bufA;
    const __half* __restrict__ srcI = src + (size_t)img * IMG;
    __half*       __restrict__ dstI = dst + (size_t)img * IMG + col;
    const float* __restrict__ lgI = logits + (size_t)imgF * IMG;
    const int*   __restrict__ tgI = target + (size_t)imgF * IMG;

    auto ldm = [&](int r) -> Row {
        Row R;
        R.m[0] = R.m[1] = R.m[2] = R.m[3] = PINF2();
        R.h = PINF2();
        if ((unsigned)r < (unsigned)HH) {
            if (MODE == 0) {
                if (isPred) {
                    float4 t0 = __ldg((const float4*)(lgI + r * WW + col));
                    float4 t1 = __ldg((const float4*)(lgI + r * WW + col + 4));
                    R.m[0] = __floats2half2_rn(sig1(t0.x), sig1(t0.y));
                    R.m[1] = __floats2half2_rn(sig1(t0.z), sig1(t0.w));
                    R.m[2] = __floats2half2_rn(sig1(t1.x), sig1(t1.y));
                    R.m[3] = __floats2half2_rn(sig1(t1.z), sig1(t1.w));
                    if (hv) {
                        float2 t = __ldg((const float2*)(lgI + r * WW + hcol));
                        R.h = __floats2half2_rn(sig1(t.x), sig1(t.y));
                    }
                } else {
                    int4 t0 = __ldg((const int4*)(tgI + r * WW + col));
                    int4 t1 = __ldg((const int4*)(tgI + r * WW + col + 4));
                    R.m[0] = __floats2half2_rn((float)t0.x, (float)t0.y);
                    R.m[1] = __floats2half2_rn((float)t0.z, (float)t0.w);
                    R.m[2] = __floats2half2_rn((float)t1.x, (float)t1.y);
                    R.m[3] = __floats2half2_rn((float)t1.z, (float)t1.w);
                    if (hv) {
                        int2 t = __ldg((const int2*)(tgI + r * WW + hcol));
                        R.h = __floats2half2_rn((float)t.x, (float)t.y);
                    }
                }
            } else {
                uint4 t = __ldg((const uint4*)(srcI + r * WW + col));
                R.m[0] = H(t.x); R.m[1] = H(t.y); R.m[2] = H(t.z); R.m[3] = H(t.w);
                if (hv) {
                    unsigned th = __ldg((const unsigned*)(srcI + r * WW + hcol));
                    R.h = H(th);
                }
            }
        }
        return R;
    };

    // erode rows A,B,C -> E[4] (own 8 cols) + EHw (halo word: high=left e(-1), low=right e(256))
    auto erode = [&](const Row& A, const Row& B, const Row& C,
                     __half2 E[4], __half2& EHw) {
        __half2 vm0 = __hmin2(__hmin2(A.m[0], B.m[0]), C.m[0]);
        __half2 vm1 = __hmin2(__hmin2(A.m[1], B.m[1]), C.m[1]);
        __half2 vm2 = __hmin2(__hmin2(A.m[2], B.m[2]), C.m[2]);
        __half2 vm3 = __hmin2(__hmin2(A.m[3], B.m[3]), C.m[3]);
        __half2 hv2 = __hmin2(__hmin2(A.h,    B.h),    C.h);

        unsigned prev3 = __shfl_up_sync(0xffffffffu, U(vm3), 1);
        unsigned next0 = __shfl_down_sync(0xffffffffu, U(vm0), 1);
        if (hl) prev3 = U(hv2);
        if (hr) next0 = U(hv2);

        __half2 sr0 = mid(H(prev3), vm0);
        __half2 sr1 = mid(vm0, vm1);
        __half2 sr2 = mid(vm1, vm2);
        __half2 sr3 = mid(vm2, vm3);
        __half2 sl3 = mid(vm3, H(next0));

        E[0] = __hmin2(__hmin2(sr0, vm0), sr1);
        E[1] = __hmin2(__hmin2(sr1, vm1), sr2);
        E[2] = __hmin2(__hmin2(sr2, vm2), sr3);
        E[3] = __hmin2(__hmin2(sr3, vm3), sl3);

        __half lo = __low2half(hv2), hi = __high2half(hv2);
        __half m2 = __hmin(lo, hi);
        __half eL = __hmin(m2, __low2half(vm0));    // eroded(col base-1), lane0
        __half eR = __hmin(m2, __high2half(vm3));   // eroded(col base+256), lane31
        EHw = __halves2half2(eR, eL);
        if (hedge) EHw = NINF2();
    };

    const int r0 = seg * SEG;

    Row a = ldm(r0 - 2), b = ldm(r0 - 1), c = ldm(r0), cn = ldm(r0 + 1);

    __half2 e0[4], e1[4], e2[4];
    __half2 eh0, eh1, eh2;

    erode(a, b, c, e0, eh0);                   // eroded(r0-1)
    if (r0 - 1 < 0) {
        e0[0] = e0[1] = e0[2] = e0[3] = NINF2(); eh0 = NINF2();
    }

    a = b; b = c; c = cn; cn = ldm(r0 + 2);
    erode(a, b, c, e1, eh1);                   // eroded(r0)

    float acc = 0.0f;

#pragma unroll 4
    for (int oy = r0; oy < r0 + SEG; ++oy) {
        a = b; b = c; c = cn; cn = ldm(oy + 3);

        erode(a, b, c, e2, eh2);               // eroded(oy+1)
        if (oy + 1 >= HH) {
            e2[0] = e2[1] = e2[2] = e2[3] = NINF2(); eh2 = NINF2();
        }

        // dilation of eroded rows oy-1..oy+1
        __half2 om0 = __hmax2(__hmax2(e0[0], e1[0]), e2[0]);
        __half2 om1 = __hmax2(__hmax2(e0[1], e1[1]), e2[1]);
        __half2 om2 = __hmax2(__hmax2(e0[2], e1[2]), e2[2]);
        __half2 om3 = __hmax2(__hmax2(e0[3], e1[3]), e2[3]);
        __half2 omh = __hmax2(__hmax2(eh0,   eh1),   eh2);

        unsigned prev3 = __shfl_up_sync(0xffffffffu, U(om3), 1);
        unsigned next0 = __shfl_down_sync(0xffffffffu, U(om0), 1);
        if (hl) prev3 = U(omh);    // high half = opened-source at col -1
        if (hr) next0 = U(omh);    // low half  = opened-source at col 256

        __half2 sr0 = mid(H(prev3), om0);
        __half2 sr1 = mid(om0, om1);
        __half2 sr2 = mid(om1, om2);
        __half2 sr3 = mid(om2, om3);
        __half2 sl3 = mid(om3, H(next0));

        __half2 op0 = __hmax2(__hmax2(sr0, om0), sr1);
        __half2 op1 = __hmax2(__hmax2(sr1, om1), sr2);
        __half2 op2 = __hmax2(__hmax2(sr2, om2), sr3);
        __half2 op3 = __hmax2(__hmax2(sr3, om3), sl3);

        // out = clip(x - (opened - eroded), 0, 1); a == x[oy], e1 == eroded(oy)
        __half2 o0 = __hsub2_sat(a.m[0], __hsub2(op0, e1[0]));
        __half2 o1 = __hsub2_sat(a.m[1], __hsub2(op1, e1[1]));
        __half2 o2 = __hsub2_sat(a.m[2], __hsub2(op2, e1[2]));
        __half2 o3 = __hsub2_sat(a.m[3], __hsub2(op3, e1[3]));

        if (MODE < 2) {
            uint4 st; st.x = U(o0); st.y = U(o1); st.z = U(o2); st.w = U(o3);
            *(uint4*)(dstI + oy * WW) = st;
        } else {
            float2 f0 = __half22float2(o0), f1 = __half22float2(o1);
            float2 f2 = __half22float2(o2), f3 = __half22float2(o3);
            if (isPred) {   // tp += skel_pred * target
                int4 t0 = __ldg((const int4*)(tgI + oy * WW + col));
                int4 t1 = __ldg((const int4*)(tgI + oy * WW + col + 4));
                acc += f0.x * (float)t0.x + f0.y * (float)t0.y
                     + f1.x * (float)t0.z + f1.y * (float)t0.w
                     + f2.x * (float)t1.x + f2.y * (float)t1.y
                     + f3.x * (float)t1.z + f3.y * (float)t1.w;
            } else {        // ts += skel_gt * sigmoid(logits)
                float4 t0 = __ldg((const float4*)(lgI + oy * WW + col));
                float4 t1 = __ldg((const float4*)(lgI + oy * WW + col + 4));
                acc += f0.x * sig1(t0.x) + f0.y * sig1(t0.y)
                     + f1.x * sig1(t0.z) + f1.y * sig1(t0.w)
                     + f2.x * sig1(t1.x) + f2.y * sig1(t1.y)
                     + f3.x * sig1(t1.z) + f3.y * sig1(t1.w);
            }
        }

        e0[0] = e1[0]; e0[1] = e1[1]; e0[2] = e1[2]; e0[3] = e1[3];
        e1[0] = e2[0]; e1[1] = e2[1]; e1[2] = e2[2]; e1[3] = e2[3];
        eh0 = eh1; eh1 = eh2;
    }

    if (MODE == 2) {
        for (int o = 16; o > 0; o >>= 1)
            acc += __shfl_down_sync(0xffffffffu, acc, o);
        __shared__ float s[WPB];
        if (lane == 0) s[w] = acc;
        __syncthreads();
        if (threadIdx.x == 0) {
            float t = 0.0f;
#pragma unroll
            for (int i = 0; i < WPB; ++i) t += s[i];
            g_part[blockIdx.x] = t;
        }
    }
}

// ---------------------------------------------------------------------------
__global__ void final_kernel(float* __restrict__ out)
{
    int t = threadIdx.x;   // 32 threads
    float contrib = 0.0f;
    if (t < 16) {
        double tp = 0.0, ts = 0.0;
        for (int k = 0; k < BLOCKS_PER_IMG; ++k) {
            tp += (double)g_part[t * BLOCKS_PER_IMG + k];
            ts += (double)g_part[(t + 16) * BLOCKS_PER_IMG + k];
        }
        const double eps = 1e-6;
        double den = tp + ts;
        double cl = (den > 0.0) ? (2.0 * tp * ts + eps) / (den + eps) : 1.0;
        cl = fmin(fmax(cl, 0.0), 1.0);
        contrib = (float)(1.0 - cl);
    }
    for (int o = 16; o > 0; o >>= 1)
        contrib += __shfl_down_sync(0xffffffffu, contrib, o);
    if (t == 0) out[0] = contrib * (1.0f / 16.0f);
}

// ---------------------------------------------------------------------------
extern "C" void kernel_launch(void* const* d_in, const int* in_sizes, int n_in,
                              void* d_out, int out_size)
{
    (void)in_sizes; (void)n_in; (void)out_size;
    const float* lg = (const float*)d_in[0];
    const int*   tg = (const int*)d_in[1];
    float*       out = (float*)d_out;

    // iter1 (fused sigmoid/convert) -> bufB
    skel_kernel<0><<<NBLOCKS, WPB * 32>>>(1, lg, tg);
    // iter2: B -> A
    skel_kernel<1><<<NBLOCKS, WPB * 32>>>(0, lg, tg);
    // iter3: A -> B
    skel_kernel<1><<<NBLOCKS, WPB * 32>>>(1, lg, tg);
    // iter4: B -> A
    skel_kernel<1><<<NBLOCKS, WPB * 32>>>(0, lg, tg);
    // iter5 (fused reduce): A -> partials
    skel_kernel<2><<<NBLOCKS, WPB * 32>>>(1, lg, tg);

    final_kernel<<<1, 32>>>(out);
}

// round 5
// speedup vs baseline: 1.7612x; 1.0138x over previous
#include <cuda_runtime.h>
#include <cuda_fp16.h>
#include <cstring>

// ---------------------------------------------------------------------------
// clDice loss, 3-pass fused:
//   P1: iter1 from inputs (sigmoid/convert) -> bufB          [single kernel]
//   P2: iters 2+3 fused, bufB -> bufA                        [fused kernel]
//   P3: iters 4+5 fused + tp/ts reduction (no store)         [fused kernel]
// Warp-strip stencil, half2 SIMD, all intermediate rows in registers.
// ---------------------------------------------------------------------------

#define HH 1024
#define WW 1024
#define IMG (HH * WW)

__device__ __half g_bufA[(size_t)32 * IMG];   // 64 MB
__device__ __half g_bufB[(size_t)32 * IMG];   // 64 MB
__device__ float  g_part[1024];

// ---- helpers --------------------------------------------------------------
__device__ __forceinline__ unsigned U(__half2 h) { unsigned u; memcpy(&u, &h, 4); return u; }
__device__ __forceinline__ __half2  H(unsigned u) { __half2 h; memcpy(&h, &u, 4); return h; }
__device__ __forceinline__ __half2  PINF2() { return H(0x7C007C00u); }
__device__ __forceinline__ __half2  NINF2() { return H(0xFC00FC00u); }
__device__ __forceinline__ __half   NINF1() { return __ushort_as_half((unsigned short)0xFC00); }
__device__ __forceinline__ float    sig1(float x) { return 1.0f / (1.0f + __expf(-x)); }
__device__ __forceinline__ __half2  mid(__half2 a, __half2 b) { return H(__byte_perm(U(a), U(b), 0x5432)); }
__device__ __forceinline__ __half2  swp(__half2 a) { return H(__byte_perm(U(a), 0, 0x1032)); }
__device__ __forceinline__ __half2  dupl(__half2 a) { return H(__byte_perm(U(a), 0, 0x1010)); }
__device__ __forceinline__ __half2  min3h2(__half2 a, __half2 b, __half2 c) { return __hmin2(__hmin2(a, b), c); }
__device__ __forceinline__ __half2  max3h2(__half2 a, __half2 b, __half2 c) { return __hmax2(__hmax2(a, b), c); }
__device__ __forceinline__ __half2  shup(__half2 v) { return H(__shfl_up_sync(0xffffffffu, U(v), 1)); }
__device__ __forceinline__ __half2  shdn(__half2 v) { return H(__shfl_down_sync(0xffffffffu, U(v), 1)); }

// ===========================================================================
// P1: single iteration from raw inputs (round-4 proven code, MODE0 only)
// Warp = 256 cols (8/lane), SEG 32 rows. grid 512 x 256thr.
// ===========================================================================
constexpr int S1_SEG = 32;
constexpr int S1_STRIPS = 4;
constexpr int S1_WPB = 8;
constexpr int S1_BPI = (S1_STRIPS * (HH / S1_SEG)) / S1_WPB;   // 16
constexpr int S1_GRID = 32 * S1_BPI;                           // 512

struct Row1 { __half2 m[4]; __half2 h; };

__global__ __launch_bounds__(S1_WPB * 32)
void init_iter_kernel(const float* __restrict__ logits, const int* __restrict__ target)
{
    const int lane = threadIdx.x & 31;
    const int w    = threadIdx.x >> 5;
    const int img  = blockIdx.x / S1_BPI;
    const bool isPred = (img < 16);
    const int imgF = img & 15;
    const int u    = (blockIdx.x % S1_BPI) * S1_WPB + w;
    const int strip = u & (S1_STRIPS - 1);
    const int seg   = u >> 2;
    const int colBase = strip * 256;
    const int col     = colBase + lane * 8;

    const bool hl = (lane == 0);
    const bool hr = (lane == 31);
    const bool hv = (hl && strip > 0) || (hr && strip < S1_STRIPS - 1);
    const bool hedge = (hl && strip == 0) || (hr && strip == S1_STRIPS - 1);
    const int  hcol  = hl ? (colBase - 2) : (colBase + 256);

    __half* __restrict__ dstI = g_bufB + (size_t)img * IMG + col;
    const float* __restrict__ lgI = logits + (size_t)imgF * IMG;
    const int*   __restrict__ tgI = target + (size_t)imgF * IMG;

    auto ldm = [&](int r) -> Row1 {
        Row1 R;
        R.m[0] = R.m[1] = R.m[2] = R.m[3] = PINF2();
        R.h = PINF2();
        if ((unsigned)r < (unsigned)HH) {
            if (isPred) {
                float4 t0 = __ldg((const float4*)(lgI + r * WW + col));
                float4 t1 = __ldg((const float4*)(lgI + r * WW + col + 4));
                R.m[0] = __floats2half2_rn(sig1(t0.x), sig1(t0.y));
                R.m[1] = __floats2half2_rn(sig1(t0.z), sig1(t0.w));
                R.m[2] = __floats2half2_rn(sig1(t1.x), sig1(t1.y));
                R.m[3] = __floats2half2_rn(sig1(t1.z), sig1(t1.w));
                if (hv) {
                    float2 t = __ldg((const float2*)(lgI + r * WW + hcol));
                    R.h = __floats2half2_rn(sig1(t.x), sig1(t.y));
                }
            } else {
                int4 t0 = __ldg((const int4*)(tgI + r * WW + col));
                int4 t1 = __ldg((const int4*)(tgI + r * WW + col + 4));
                R.m[0] = __floats2half2_rn((float)t0.x, (float)t0.y);
                R.m[1] = __floats2half2_rn((float)t0.z, (float)t0.w);
                R.m[2] = __floats2half2_rn((float)t1.x, (float)t1.y);
                R.m[3] = __floats2half2_rn((float)t1.z, (float)t1.w);
                if (hv) {
                    int2 t = __ldg((const int2*)(tgI + r * WW + hcol));
                    R.h = __floats2half2_rn((float)t.x, (float)t.y);
                }
            }
        }
        return R;
    };

    auto erode = [&](const Row1& A, const Row1& B, const Row1& C,
                     __half2 E[4], __half2& EHw) {
        __half2 vm0 = min3h2(A.m[0], B.m[0], C.m[0]);
        __half2 vm1 = min3h2(A.m[1], B.m[1], C.m[1]);
        __half2 vm2 = min3h2(A.m[2], B.m[2], C.m[2]);
        __half2 vm3 = min3h2(A.m[3], B.m[3], C.m[3]);
        __half2 hv2 = min3h2(A.h,    B.h,    C.h);

        __half2 p3 = shup(vm3), n0 = shdn(vm0);
        if (hl) p3 = hv2;
        if (hr) n0 = hv2;
        __half2 sr0 = mid(p3, vm0), sr1 = mid(vm0, vm1), sr2 = mid(vm1, vm2),
                sr3 = mid(vm2, vm3), sl3 = mid(vm3, n0);
        E[0] = min3h2(sr0, vm0, sr1);
        E[1] = min3h2(sr1, vm1, sr2);
        E[2] = min3h2(sr2, vm2, sr3);
        E[3] = min3h2(sr3, vm3, sl3);

        __half lo = __low2half(hv2), hi = __high2half(hv2);
        __half m2 = __hmin(lo, hi);
        __half eL = __hmin(m2, __low2half(vm0));
        __half eR = __hmin(m2, __high2half(vm3));
        EHw = __halves2half2(eR, eL);
        if (hedge) EHw = NINF2();
    };

    const int r0 = seg * S1_SEG;
    Row1 a = ldm(r0 - 2), b = ldm(r0 - 1), c = ldm(r0), cn = ldm(r0 + 1);
    __half2 e0[4], e1[4], e2[4];
    __half2 eh0, eh1, eh2;

    erode(a, b, c, e0, eh0);
    if (r0 - 1 < 0) { e0[0] = e0[1] = e0[2] = e0[3] = NINF2(); eh0 = NINF2(); }
    a = b; b = c; c = cn; cn = ldm(r0 + 2);
    erode(a, b, c, e1, eh1);

#pragma unroll 4
    for (int oy = r0; oy < r0 + S1_SEG; ++oy) {
        a = b; b = c; c = cn; cn = ldm(oy + 3);
        erode(a, b, c, e2, eh2);
        if (oy + 1 >= HH) { e2[0] = e2[1] = e2[2] = e2[3] = NINF2(); eh2 = NINF2(); }

        __half2 om0 = max3h2(e0[0], e1[0], e2[0]);
        __half2 om1 = max3h2(e0[1], e1[1], e2[1]);
        __half2 om2 = max3h2(e0[2], e1[2], e2[2]);
        __half2 om3 = max3h2(e0[3], e1[3], e2[3]);
        __half2 omh = max3h2(eh0, eh1, eh2);

        __half2 p3 = shup(om3), n0 = shdn(om0);
        if (hl) p3 = omh;
        if (hr) n0 = omh;
        __half2 sr0 = mid(p3, om0), sr1 = mid(om0, om1), sr2 = mid(om1, om2),
                sr3 = mid(om2, om3), sl3 = mid(om3, n0);
        __half2 op0 = max3h2(sr0, om0, sr1);
        __half2 op1 = max3h2(sr1, om1, sr2);
        __half2 op2 = max3h2(sr2, om2, sr3);
        __half2 op3 = max3h2(sr3, om3, sl3);

        uint4 st;
        st.x = U(__hsub2_sat(a.m[0], __hsub2(op0, e1[0])));
        st.y = U(__hsub2_sat(a.m[1], __hsub2(op1, e1[1])));
        st.z = U(__hsub2_sat(a.m[2], __hsub2(op2, e1[2])));
        st.w = U(__hsub2_sat(a.m[3], __hsub2(op3, e1[3])));
        *(uint4*)(dstI + oy * WW) = st;

        e0[0] = e1[0]; e0[1] = e1[1]; e0[2] = e1[2]; e0[3] = e1[3];
        e1[0] = e2[0]; e1[1] = e2[1]; e1[2] = e2[2]; e1[3] = e2[3];
        eh0 = eh1; eh1 = eh2;
    }
}

// ===========================================================================
// Fused 2-iteration kernel. RED=0: store x''; RED=1: accumulate tp/ts.
// Warp = 256 cols, SEG 32 rows, 128-thread blocks, grid 1024.
// Halo: 4 input cols per side, packed as outward chains (uniform L/R math).
// ===========================================================================
constexpr int F_SEG = 32;
constexpr int F_WPB = 4;
constexpr int F_BPI = (4 * (HH / F_SEG)) / F_WPB;   // 32
constexpr int F_GRID = 32 * F_BPI;                  // 1024

struct XRow  { __half2 m0, m1, m2, m3, q1, q2; };   // q = outward chain (c1,c2),(c3,c4)
struct S1E   { __half2 E0, E1, E2, E3, ehA; __half eh3; };  // ehA=(e_h1,e_h2)
struct XPRow { __half2 m0, m1, m2, m3, hq; };       // hq = (xp_h1, xp_h2) chain
struct S2E   { __half2 E0, E1, E2, E3; __half eh1; };

template<int RED>
__global__ __launch_bounds__(F_WPB * 32)
void fused_kernel(int srcIsA,
                  const float* __restrict__ logits,
                  const int* __restrict__ target)
{
    const int lane = threadIdx.x & 31;
    const int w    = threadIdx.x >> 5;
    const int img  = blockIdx.x / F_BPI;
    const bool isPred = (img < 16);
    const int imgF = img & 15;
    const int u    = (blockIdx.x % F_BPI) * F_WPB + w;
    const int strip = u & 3;
    const int seg   = u >> 2;
    const int colBase = strip * 256;
    const int col     = colBase + lane * 8;

    const bool hl = (lane == 0);
    const bool hr = (lane == 31);
    const bool hv = (hl && strip > 0) || (hr && strip < 3);
    const bool hedge = (hl && strip == 0) || (hr && strip == 3);
    const int  hcol  = hl ? (colBase - 4) : (colBase + 256);

    const __half* src = srcIsA ? g_bufA : g_bufB;
    __half*       dst = srcIsA ? g_bufB : g_bufA;
    const __half* __restrict__ srcI = src + (size_t)img * IMG;
    __half*       __restrict__ dstI = dst + (size_t)img * IMG + col;
    const float* __restrict__ lgI = logits + (size_t)imgF * IMG;
    const int*   __restrict__ tgI = target + (size_t)imgF * IMG;

    auto ldx = [&](int r) -> XRow {
        XRow R;
        R.m0 = R.m1 = R.m2 = R.m3 = PINF2();
        R.q1 = R.q2 = PINF2();
        if ((unsigned)r < (unsigned)HH) {
            const __half* rp = srcI + r * WW;
            uint4 t = __ldg((const uint4*)(rp + col));
            R.m0 = H(t.x); R.m1 = H(t.y); R.m2 = H(t.z); R.m3 = H(t.w);
            if (hv) {
                uint2 u2 = __ldg((const uint2*)(rp + hcol));
                __half2 A = H(u2.x), B = H(u2.y);
                if (hl) { R.q1 = swp(B); R.q2 = swp(A); }   // reverse to outward order
                else    { R.q1 = A;      R.q2 = B; }
            }
        }
        return R;
    };

    auto erode1 = [&](const XRow& A, const XRow& B, const XRow& C) -> S1E {
        __half2 vm0 = min3h2(A.m0, B.m0, C.m0);
        __half2 vm1 = min3h2(A.m1, B.m1, C.m1);
        __half2 vm2 = min3h2(A.m2, B.m2, C.m2);
        __half2 vm3 = min3h2(A.m3, B.m3, C.m3);
        __half2 vq1 = min3h2(A.q1, B.q1, C.q1);
        __half2 vq2 = min3h2(A.q2, B.q2, C.q2);

        __half2 W = dupl(vq1);                  // vm at dist-1 (both halves)
        __half2 p3 = shup(vm3), n0 = shdn(vm0);
        if (hl) p3 = W;
        if (hr) n0 = W;
        __half2 sr0 = mid(p3, vm0), sr1 = mid(vm0, vm1), sr2 = mid(vm1, vm2),
                sr3 = mid(vm2, vm3), sl3 = mid(vm3, n0);
        S1E e;
        e.E0 = min3h2(sr0, vm0, sr1);
        e.E1 = min3h2(sr1, vm1, sr2);
        e.E2 = min3h2(sr2, vm2, sr3);
        e.E3 = min3h2(sr3, vm3, sl3);

        __half p0 = hl ? __low2half(vm0) : __high2half(vm3);   // inner vm
        __half2 A2 = __halves2half2(p0, __low2half(vq1));      // (d0,d1)
        __half2 C2 = mid(vq1, vq2);                            // (d2,d3)
        e.ehA = min3h2(A2, vq1, C2);                           // (e_h1,e_h2)
        e.eh3 = __hmin(__hmin(__high2half(vq1), __low2half(vq2)), __high2half(vq2));
        if (hedge) { e.ehA = NINF2(); e.eh3 = NINF1(); }
        return e;
    };
    auto fix1 = [&](S1E e, int r) -> S1E {
        if (r < 0 || r >= HH) {
            e.E0 = e.E1 = e.E2 = e.E3 = NINF2();
            e.ehA = NINF2(); e.eh3 = NINF1();
        }
        return e;
    };

    auto open1 = [&](const S1E& P, const S1E& M, const S1E& N,
                     const XRow& xr, int row) -> XPRow {
        __half2 om0 = max3h2(P.E0, M.E0, N.E0);
        __half2 om1 = max3h2(P.E1, M.E1, N.E1);
        __half2 om2 = max3h2(P.E2, M.E2, N.E2);
        __half2 om3 = max3h2(P.E3, M.E3, N.E3);
        __half2 omA = max3h2(P.ehA, M.ehA, N.ehA);
        __half  om3h = __hmax(__hmax(P.eh3, M.eh3), N.eh3);

        __half2 W = dupl(omA);
        __half2 p3 = shup(om3), n0 = shdn(om0);
        if (hl) p3 = W;
        if (hr) n0 = W;
        __half2 sr0 = mid(p3, om0), sr1 = mid(om0, om1), sr2 = mid(om1, om2),
                sr3 = mid(om2, om3), sl3 = mid(om3, n0);
        __half2 op0 = max3h2(sr0, om0, sr1);
        __half2 op1 = max3h2(sr1, om1, sr2);
        __half2 op2 = max3h2(sr2, om2, sr3);
        __half2 op3 = max3h2(sr3, om3, sl3);

        XPRow o;
        o.m0 = __hsub2_sat(xr.m0, __hsub2(op0, M.E0));
        o.m1 = __hsub2_sat(xr.m1, __hsub2(op1, M.E1));
        o.m2 = __hsub2_sat(xr.m2, __hsub2(op2, M.E2));
        o.m3 = __hsub2_sat(xr.m3, __hsub2(op3, M.E3));

        __half p0 = hl ? __low2half(om0) : __high2half(om3);
        __half2 A2 = __halves2half2(p0, __low2half(omA));
        __half2 C2 = __halves2half2(__high2half(omA), om3h);
        __half2 opA = max3h2(A2, omA, C2);               // (op_h1, op_h2)
        o.hq = __hsub2_sat(xr.q1, __hsub2(opA, M.ehA));
        if (hedge) o.hq = PINF2();
        if (row < 0 || row >= HH) { o.m0 = o.m1 = o.m2 = o.m3 = PINF2(); o.hq = PINF2(); }
        return o;
    };

    auto erode2 = [&](const XPRow& A, const XPRow& B, const XPRow& C) -> S2E {
        __half2 vm0 = min3h2(A.m0, B.m0, C.m0);
        __half2 vm1 = min3h2(A.m1, B.m1, C.m1);
        __half2 vm2 = min3h2(A.m2, B.m2, C.m2);
        __half2 vm3 = min3h2(A.m3, B.m3, C.m3);
        __half2 vq  = min3h2(A.hq, B.hq, C.hq);

        __half2 W = dupl(vq);
        __half2 p3 = shup(vm3), n0 = shdn(vm0);
        if (hl) p3 = W;
        if (hr) n0 = W;
        __half2 sr0 = mid(p3, vm0), sr1 = mid(vm0, vm1), sr2 = mid(vm1, vm2),
                sr3 = mid(vm2, vm3), sl3 = mid(vm3, n0);
        S2E e;
        e.E0 = min3h2(sr0, vm0, sr1);
        e.E1 = min3h2(sr1, vm1, sr2);
        e.E2 = min3h2(sr2, vm2, sr3);
        e.E3 = min3h2(sr3, vm3, sl3);

        __half p0 = hl ? __low2half(vm0) : __high2half(vm3);
        e.eh1 = __hmin(__hmin(p0, __low2half(vq)), __high2half(vq));
        if (hedge) e.eh1 = NINF1();
        return e;
    };
    auto fix2 = [&](S2E e, int r) -> S2E {
        if (r < 0 || r >= HH) {
            e.E0 = e.E1 = e.E2 = e.E3 = NINF2();
            e.eh1 = NINF1();
        }
        return e;
    };

    auto open2 = [&](const S2E& P, const S2E& M, const S2E& N, const XPRow& xr,
                     __half2& o0, __half2& o1, __half2& o2, __half2& o3) {
        __half2 om0 = max3h2(P.E0, M.E0, N.E0);
        __half2 om1 = max3h2(P.E1, M.E1, N.E1);
        __half2 om2 = max3h2(P.E2, M.E2, N.E2);
        __half2 om3 = max3h2(P.E3, M.E3, N.E3);
        __half2 W = __half2half2(__hmax(__hmax(P.eh1, M.eh1), N.eh1));

        __half2 p3 = shup(om3), n0 = shdn(om0);
        if (hl) p3 = W;
        if (hr) n0 = W;
        __half2 sr0 = mid(p3, om0), sr1 = mid(om0, om1), sr2 = mid(om1, om2),
                sr3 = mid(om2, om3), sl3 = mid(om3, n0);
        o0 = __hsub2_sat(xr.m0, __hsub2(max3h2(sr0, om0, sr1), M.E0));
        o1 = __hsub2_sat(xr.m1, __hsub2(max3h2(sr1, om1, sr2), M.E1));
        o2 = __hsub2_sat(xr.m2, __hsub2(max3h2(sr2, om2, sr3), M.E2));
        o3 = __hsub2_sat(xr.m3, __hsub2(max3h2(sr3, om3, sl3), M.E3));
    };

    // ---- warm-up ----
    const int r0 = seg * F_SEG;
    XRow a = ldx(r0 - 4), b = ldx(r0 - 3), c = ldx(r0 - 2), cn = ldx(r0 - 1);

    S1E es0 = fix1(erode1(a, b, c), r0 - 3);
    a = b; b = c; c = cn; cn = ldx(r0);
    S1E es1 = fix1(erode1(a, b, c), r0 - 2);
    a = b; b = c; c = cn; cn = ldx(r0 + 1);
    S1E es2 = fix1(erode1(a, b, c), r0 - 1);
    XPRow xp_a = open1(es0, es1, es2, a, r0 - 2);       // x'(r0-2); a = x(r0-2)
    es0 = es1; es1 = es2;
    a = b; b = c; c = cn; cn = ldx(r0 + 2);
    es2 = fix1(erode1(a, b, c), r0);
    XPRow xp_b = open1(es0, es1, es2, a, r0 - 1);       // x'(r0-1)
    es0 = es1; es1 = es2;
    a = b; b = c; c = cn; cn = ldx(r0 + 3);
    es2 = fix1(erode1(a, b, c), r0 + 1);
    XPRow xp_c = open1(es0, es1, es2, a, r0);           // x'(r0)
    S2E ep0 = fix2(erode2(xp_a, xp_b, xp_c), r0 - 1);   // e'(r0-1)
    es0 = es1; es1 = es2;
    a = b; b = c; c = cn; cn = ldx(r0 + 4);
    es2 = fix1(erode1(a, b, c), r0 + 2);
    xp_a = xp_b; xp_b = xp_c;
    xp_c = open1(es0, es1, es2, a, r0 + 1);             // x'(r0+1)
    S2E ep1 = fix2(erode2(xp_a, xp_b, xp_c), r0);       // e'(r0)
    es0 = es1; es1 = es2;
    // invariants: a=x(r0+1), b=x(r0+2), c=x(r0+3), cn=x(r0+4)
    //             es0=e(r0+1), es1=e(r0+2); xp_{a,b,c}=x'(r0-1..r0+1)

    float acc = 0.0f;

#pragma unroll 1
    for (int oy = r0; oy < r0 + F_SEG; ++oy) {
        a = b; b = c; c = cn; cn = ldx(oy + 5);
        S1E esn = fix1(erode1(a, b, c), oy + 3);        // e(oy+3); a=x(oy+2)
        xp_a = xp_b; xp_b = xp_c;
        xp_c = open1(es0, es1, esn, a, oy + 2);         // x'(oy+2)
        S2E ep2 = fix2(erode2(xp_a, xp_b, xp_c), oy + 1);

        __half2 o0, o1, o2, o3;
        open2(ep0, ep1, ep2, xp_a, o0, o1, o2, o3);     // x''(oy); xp_a = x'(oy)

        if (RED == 0) {
            uint4 st; st.x = U(o0); st.y = U(o1); st.z = U(o2); st.w = U(o3);
            *(uint4*)(dstI + oy * WW) = st;
        } else {
            float2 f0 = __half22float2(o0), f1 = __half22float2(o1);
            float2 f2 = __half22float2(o2), f3 = __half22float2(o3);
            if (isPred) {
                int4 t0 = __ldg((const int4*)(tgI + oy * WW + col));
                int4 t1 = __ldg((const int4*)(tgI + oy * WW + col + 4));
                acc += f0.x * (float)t0.x + f0.y * (float)t0.y
                     + f1.x * (float)t0.z + f1.y * (float)t0.w
                     + f2.x * (float)t1.x + f2.y * (float)t1.y
                     + f3.x * (float)t1.z + f3.y * (float)t1.w;
            } else {
                float4 t0 = __ldg((const float4*)(lgI + oy * WW + col));
                float4 t1 = __ldg((const float4*)(lgI + oy * WW + col + 4));
                acc += f0.x * sig1(t0.x) + f0.y * sig1(t0.y)
                     + f1.x * sig1(t0.z) + f1.y * sig1(t0.w)
                     + f2.x * sig1(t1.x) + f2.y * sig1(t1.y)
                     + f3.x * sig1(t1.z) + f3.y * sig1(t1.w);
            }
        }

        es0 = es1; es1 = esn;
        ep0 = ep1; ep1 = ep2;
    }

    if (RED == 1) {
        for (int o = 16; o > 0; o >>= 1)
            acc += __shfl_down_sync(0xffffffffu, acc, o);
        __shared__ float s[F_WPB];
        if (lane == 0) s[w] = acc;
        __syncthreads();
        if (threadIdx.x == 0) {
            float t = 0.0f;
#pragma unroll
            for (int i = 0; i < F_WPB; ++i) t += s[i];
            g_part[blockIdx.x] = t;
        }
    }
}

// ---------------------------------------------------------------------------
__global__ void final_kernel(float* __restrict__ out)
{
    int t = threadIdx.x;   // 32 threads
    float contrib = 0.0f;
    if (t < 16) {
        double tp = 0.0, ts = 0.0;
        for (int k = 0; k < F_BPI; ++k) {
            tp += (double)g_part[t * F_BPI + k];
            ts += (double)g_part[16 * F_BPI + t * F_BPI + k];
        }
        const double eps = 1e-6;
        double den = tp + ts;
        double cl = (den > 0.0) ? (2.0 * tp * ts + eps) / (den + eps) : 1.0;
        cl = fmin(fmax(cl, 0.0), 1.0);
        contrib = (float)(1.0 - cl);
    }
    for (int o = 16; o > 0; o >>= 1)
        contrib += __shfl_down_sync(0xffffffffu, contrib, o);
    if (t == 0) out[0] = contrib * (1.0f / 16.0f);
}

// ---------------------------------------------------------------------------
extern "C" void kernel_launch(void* const* d_in, const int* in_sizes, int n_in,
                              void* d_out, int out_size)
{
    (void)in_sizes; (void)n_in; (void)out_size;
    const float* lg = (const float*)d_in[0];
    const int*   tg = (const int*)d_in[1];
    float*       out = (float*)d_out;

    // P1: iter1 from inputs -> bufB
    init_iter_kernel<<<S1_GRID, S1_WPB * 32>>>(lg, tg);
    // P2: iters 2+3 fused, bufB -> bufA
    fused_kernel<0><<<F_GRID, F_WPB * 32>>>(0, lg, tg);
    // P3: iters 4+5 fused + reduce, bufA -> partials
    fused_kernel<1><<<F_GRID, F_WPB * 32>>>(1, lg, tg);

    final_kernel<<<1, 32>>>(out);
}